// round 4
// baseline (speedup 1.0000x reference)
#include <cuda_runtime.h>
#include <math.h>

#define S_LEN 4096
#define D_MODEL 768
#define N_HEADS 12
#define D_HEAD 64

// ---------------- scratch (no allocations allowed) ----------------
__device__ float g_Q[S_LEN * D_MODEL];
__device__ float g_K[S_LEN * D_MODEL];
__device__ float g_V[S_LEN * D_MODEL];
__device__ float g_CTX[S_LEN * D_MODEL];

// ---------------- tf32 helpers ----------------
__device__ __forceinline__ unsigned cvt_tf32(float f) {
    unsigned r;
    asm("cvt.rna.tf32.f32 %0, %1;" : "=r"(r) : "f"(f));
    return r;
}
__device__ __forceinline__ float cvt_tf32f(float f) {
    return __uint_as_float(cvt_tf32(f));
}
__device__ __forceinline__ void mma_tf32(float* c, const unsigned* a, unsigned b0, unsigned b1) {
    asm volatile(
        "mma.sync.aligned.m16n8k8.row.col.f32.tf32.tf32.f32 "
        "{%0,%1,%2,%3}, {%4,%5,%6,%7}, {%8,%9}, {%0,%1,%2,%3};\n"
        : "+f"(c[0]), "+f"(c[1]), "+f"(c[2]), "+f"(c[3])
        : "r"(a[0]), "r"(a[1]), "r"(a[2]), "r"(a[3]), "r"(b0), "r"(b1));
}

// pair-interleave position of column c within its 8-wide k-group:
// col lc (0..3) -> 2*lc, col lc+4 -> 2*lc+1
__device__ __forceinline__ int pairpos(int c8) { return 2 * (c8 & 3) + (c8 >> 2); }

// ============================================================================
// GEMM (tf32): C[M,N] = (A[M,K] @ B[N,K]^T + bias[N]) * scale
// 128 threads / 4 warps. BM=128 (warp M=32), BN=64, BK=32. (unchanged, fast)
// ============================================================================
#define GBM 128
#define GBN 64
#define GBK 32
#define GAS 40
#define GBS 40

__global__ __launch_bounds__(128)
void gemm_tf32(const float* __restrict__ A, const float* __restrict__ B,
               const float* __restrict__ bias, float* __restrict__ C,
               int M, int N, int K, float scale) {
    __shared__ float Ap[GBM * GAS];
    __shared__ float Bp[GBN * GBS];

    const int tid  = threadIdx.x;
    const int warp = tid >> 5;
    const int lane = tid & 31;
    const int lr = lane >> 2;
    const int lc = lane & 3;

    const int crow = blockIdx.y * GBM;
    const int ccol = blockIdx.x * GBN;

    float acc[2][8][4];
    #pragma unroll
    for (int mf = 0; mf < 2; mf++)
        #pragma unroll
        for (int nc = 0; nc < 8; nc++)
            #pragma unroll
            for (int i = 0; i < 4; i++) acc[mf][nc][i] = 0.f;

    for (int kt = 0; kt < K; kt += GBK) {
        #pragma unroll
        for (int it = 0; it < 8; it++) {
            int t = tid + it * 128;
            int row = t >> 3;
            int c4  = (t & 7) * 4;
            float4 a4 = *reinterpret_cast<const float4*>(&A[(size_t)(crow + row) * K + kt + c4]);
            int base = row * GAS + (c4 >> 3) * 8;
            Ap[base + pairpos((c4 + 0) & 7)] = cvt_tf32f(a4.x);
            Ap[base + pairpos((c4 + 1) & 7)] = cvt_tf32f(a4.y);
            Ap[base + pairpos((c4 + 2) & 7)] = cvt_tf32f(a4.z);
            Ap[base + pairpos((c4 + 3) & 7)] = cvt_tf32f(a4.w);
        }
        #pragma unroll
        for (int it = 0; it < 4; it++) {
            int t = tid + it * 128;
            int row = t >> 3;
            int c4  = (t & 7) * 4;
            float4 b4 = *reinterpret_cast<const float4*>(&B[(size_t)(ccol + row) * K + kt + c4]);
            int base = row * GBS + (c4 >> 3) * 8;
            Bp[base + pairpos((c4 + 0) & 7)] = cvt_tf32f(b4.x);
            Bp[base + pairpos((c4 + 1) & 7)] = cvt_tf32f(b4.y);
            Bp[base + pairpos((c4 + 2) & 7)] = cvt_tf32f(b4.z);
            Bp[base + pairpos((c4 + 3) & 7)] = cvt_tf32f(b4.w);
        }
        __syncthreads();

        #pragma unroll
        for (int kc = 0; kc < GBK / 8; kc++) {
            unsigned a[2][4];
            #pragma unroll
            for (int mf = 0; mf < 2; mf++) {
                int r0 = warp * 32 + mf * 16 + lr;
                float2 p0 = *reinterpret_cast<const float2*>(&Ap[(r0    ) * GAS + kc * 8 + 2 * lc]);
                float2 p1 = *reinterpret_cast<const float2*>(&Ap[(r0 + 8) * GAS + kc * 8 + 2 * lc]);
                a[mf][0] = __float_as_uint(p0.x); a[mf][2] = __float_as_uint(p0.y);
                a[mf][1] = __float_as_uint(p1.x); a[mf][3] = __float_as_uint(p1.y);
            }
            #pragma unroll
            for (int nc = 0; nc < 8; nc++) {
                float2 bp = *reinterpret_cast<const float2*>(&Bp[(nc * 8 + lr) * GBS + kc * 8 + 2 * lc]);
                unsigned b0 = __float_as_uint(bp.x), b1 = __float_as_uint(bp.y);
                mma_tf32(acc[0][nc], a[0], b0, b1);
                mma_tf32(acc[1][nc], a[1], b0, b1);
            }
        }
        __syncthreads();
    }

    #pragma unroll
    for (int mf = 0; mf < 2; mf++) {
        int row0 = crow + warp * 32 + mf * 16 + lr;
        #pragma unroll
        for (int nc = 0; nc < 8; nc++) {
            int col = ccol + nc * 8 + 2 * lc;
            float b0 = bias[col], b1 = bias[col + 1];
            float2 v0, v1;
            v0.x = (acc[mf][nc][0] + b0) * scale;
            v0.y = (acc[mf][nc][1] + b1) * scale;
            v1.x = (acc[mf][nc][2] + b0) * scale;
            v1.y = (acc[mf][nc][3] + b1) * scale;
            *reinterpret_cast<float2*>(&C[(size_t)row0 * N + col])       = v0;
            *reinterpret_cast<float2*>(&C[(size_t)(row0 + 8) * N + col]) = v1;
        }
    }
}

// ============================================================================
// Flash attention (tf32). 128 threads / 4 warps, warp M=32 -> BQ=128.
// Q staged ONCE in smem (pair-interleaved) -> a-fragments loaded per kc,
// freeing ~64 registers vs round 3 (no spills).
// ============================================================================
#define FBQ 128
#define FBK 64
#define QS 72
#define KS 72
#define PS 72
#define Q_FLOATS (128 * QS)           // 9216
#define K_FLOATS (64 * KS)            // 4608
#define V_FLOATS (8 * 64 * 8)         // 4096
#define P_FLOATS (4 * 32 * PS)        // 9216
#define FSMEM_FLOATS (Q_FLOATS + K_FLOATS + V_FLOATS + P_FLOATS + 64)

__global__ __launch_bounds__(128)
void flash_attn_mma(const float* __restrict__ Q, const float* __restrict__ K,
                    const float* __restrict__ V, const int* __restrict__ mask,
                    float* __restrict__ Ctx) {
    extern __shared__ float sm[];
    float* Qp  = sm;                    // [128][QS] pair-interleaved along k
    float* Ksh = Qp + Q_FLOATS;         // [64][KS] pair-interleaved along k
    float* Vt  = Ksh + K_FLOATS;        // [(kc*64 + d)*8 + pairpos(key&7)]
    float* Psh = Vt + V_FLOATS;         // per warp [32][PS]
    float* msk = Psh + P_FLOATS;

    const int h  = blockIdx.y;
    const int q0 = blockIdx.x * FBQ;
    const int tid  = threadIdx.x;
    const int warp = tid >> 5;
    const int lane = tid & 31;
    const int lr = lane >> 2;
    const int lc = lane & 3;

    float* Pw = Psh + warp * 32 * PS;
    const int w32 = warp * 32;

    // stage Q once: 128 rows x 64 cols, pair-interleaved, tf32-rounded
    #pragma unroll
    for (int it = 0; it < 16; it++) {
        int t = tid + it * 128;               // 0..2047
        int row = t >> 4;                      // 0..127
        int c4  = (t & 15) * 4;                // 0..60
        float4 q4 = *reinterpret_cast<const float4*>(
            &Q[(size_t)(q0 + row) * D_MODEL + h * D_HEAD + c4]);
        int base = row * QS + (c4 >> 3) * 8;
        Qp[base + pairpos((c4 + 0) & 7)] = cvt_tf32f(q4.x);
        Qp[base + pairpos((c4 + 1) & 7)] = cvt_tf32f(q4.y);
        Qp[base + pairpos((c4 + 2) & 7)] = cvt_tf32f(q4.z);
        Qp[base + pairpos((c4 + 3) & 7)] = cvt_tf32f(q4.w);
    }

    float o[2][8][4];
    #pragma unroll
    for (int mf = 0; mf < 2; mf++)
        #pragma unroll
        for (int nc = 0; nc < 8; nc++)
            #pragma unroll
            for (int i = 0; i < 4; i++) o[mf][nc][i] = 0.f;
    float mrow[2][2] = {{-1e30f, -1e30f}, {-1e30f, -1e30f}};
    float lrow[2][2] = {{0.f, 0.f}, {0.f, 0.f}};

    for (int kt = 0; kt < S_LEN; kt += FBK) {
        __syncthreads();
        #pragma unroll
        for (int it = 0; it < 8; it++) {
            int t = tid + it * 128;
            int row = t >> 4;
            int c4  = (t & 15) * 4;
            const float* kp = K + (size_t)(kt + row) * D_MODEL + h * D_HEAD + c4;
            const float* vp = V + (size_t)(kt + row) * D_MODEL + h * D_HEAD + c4;
            float4 k4 = *reinterpret_cast<const float4*>(kp);
            float4 v4 = *reinterpret_cast<const float4*>(vp);
            int kb = row * KS + (c4 >> 3) * 8;
            Ksh[kb + pairpos((c4 + 0) & 7)] = cvt_tf32f(k4.x);
            Ksh[kb + pairpos((c4 + 1) & 7)] = cvt_tf32f(k4.y);
            Ksh[kb + pairpos((c4 + 2) & 7)] = cvt_tf32f(k4.z);
            Ksh[kb + pairpos((c4 + 3) & 7)] = cvt_tf32f(k4.w);
            int kc = row >> 3, pp = pairpos(row & 7);
            Vt[(kc * 64 + c4 + 0) * 8 + pp] = cvt_tf32f(v4.x);
            Vt[(kc * 64 + c4 + 1) * 8 + pp] = cvt_tf32f(v4.y);
            Vt[(kc * 64 + c4 + 2) * 8 + pp] = cvt_tf32f(v4.z);
            Vt[(kc * 64 + c4 + 3) * 8 + pp] = cvt_tf32f(v4.w);
        }
        if (tid < FBK) msk[tid] = (mask[kt + tid] != 0) ? 0.f : -1e30f;
        __syncthreads();

        // S = Q @ K^T ; a-fragments streamed from smem per kc
        float cs[2][8][4];
        #pragma unroll
        for (int mf = 0; mf < 2; mf++)
            #pragma unroll
            for (int nc = 0; nc < 8; nc++)
                #pragma unroll
                for (int i = 0; i < 4; i++) cs[mf][nc][i] = 0.f;
        #pragma unroll
        for (int kc = 0; kc < 8; kc++) {
            unsigned a[2][4];
            #pragma unroll
            for (int mf = 0; mf < 2; mf++) {
                int r0 = w32 + mf * 16 + lr;
                float2 p0 = *reinterpret_cast<const float2*>(&Qp[(r0    ) * QS + kc * 8 + 2 * lc]);
                float2 p1 = *reinterpret_cast<const float2*>(&Qp[(r0 + 8) * QS + kc * 8 + 2 * lc]);
                a[mf][0] = __float_as_uint(p0.x); a[mf][2] = __float_as_uint(p0.y);
                a[mf][1] = __float_as_uint(p1.x); a[mf][3] = __float_as_uint(p1.y);
            }
            #pragma unroll
            for (int nc = 0; nc < 8; nc++) {
                float2 kb = *reinterpret_cast<const float2*>(&Ksh[(nc * 8 + lr) * KS + kc * 8 + 2 * lc]);
                unsigned b0 = __float_as_uint(kb.x), b1 = __float_as_uint(kb.y);
                mma_tf32(cs[0][nc], a[0], b0, b1);
                mma_tf32(cs[1][nc], a[1], b0, b1);
            }
        }

        // mask + online softmax per m-fragment; P -> smem
        #pragma unroll
        for (int mf = 0; mf < 2; mf++) {
            #pragma unroll
            for (int nc = 0; nc < 8; nc++) {
                float mk0 = msk[nc * 8 + 2 * lc];
                float mk1 = msk[nc * 8 + 2 * lc + 1];
                cs[mf][nc][0] += mk0; cs[mf][nc][1] += mk1;
                cs[mf][nc][2] += mk0; cs[mf][nc][3] += mk1;
            }
            float mx0 = -1e30f, mx1 = -1e30f;
            #pragma unroll
            for (int nc = 0; nc < 8; nc++) {
                mx0 = fmaxf(mx0, fmaxf(cs[mf][nc][0], cs[mf][nc][1]));
                mx1 = fmaxf(mx1, fmaxf(cs[mf][nc][2], cs[mf][nc][3]));
            }
            mx0 = fmaxf(mx0, __shfl_xor_sync(0xffffffff, mx0, 1));
            mx0 = fmaxf(mx0, __shfl_xor_sync(0xffffffff, mx0, 2));
            mx1 = fmaxf(mx1, __shfl_xor_sync(0xffffffff, mx1, 1));
            mx1 = fmaxf(mx1, __shfl_xor_sync(0xffffffff, mx1, 2));

            float m0n = fmaxf(mrow[mf][0], mx0);
            float m1n = fmaxf(mrow[mf][1], mx1);
            float corr0 = __expf(mrow[mf][0] - m0n);
            float corr1 = __expf(mrow[mf][1] - m1n);
            mrow[mf][0] = m0n; mrow[mf][1] = m1n;
            lrow[mf][0] *= corr0; lrow[mf][1] *= corr1;
            #pragma unroll
            for (int nc = 0; nc < 8; nc++) {
                o[mf][nc][0] *= corr0; o[mf][nc][1] *= corr0;
                o[mf][nc][2] *= corr1; o[mf][nc][3] *= corr1;
            }
            #pragma unroll
            for (int nc = 0; nc < 8; nc++) {
                float p0 = __expf(cs[mf][nc][0] - m0n);
                float p1 = __expf(cs[mf][nc][1] - m0n);
                float p2 = __expf(cs[mf][nc][2] - m1n);
                float p3 = __expf(cs[mf][nc][3] - m1n);
                lrow[mf][0] += p0 + p1;
                lrow[mf][1] += p2 + p3;
                float2 w0; w0.x = cvt_tf32f(p0); w0.y = cvt_tf32f(p1);
                float2 w1; w1.x = cvt_tf32f(p2); w1.y = cvt_tf32f(p3);
                *reinterpret_cast<float2*>(&Pw[(mf * 16 + lr    ) * PS + nc * 8 + 2 * lc]) = w0;
                *reinterpret_cast<float2*>(&Pw[(mf * 16 + lr + 8) * PS + nc * 8 + 2 * lc]) = w1;
            }
        }
        __syncwarp();

        // O += P @ V (P written in mma-C order: col 2lc,2lc+1 -> read back
        // as pairpos layout matches: P stored at nc*8+2*lc which is exactly
        // pair-interleaved order for cols lc and lc+4? No: P was stored by
        // column index 2lc, 2lc+1 raw. A-fragment wants cols lc, lc+4 of the
        // kc-group: raw col lc is at offset lc (stored by the lane with
        // 2lc'=lc), raw col lc+4 at offset lc+4. So read scalars at kc*8+lc
        // and kc*8+lc+4 (same as round 3 -- verified correct there).
        #pragma unroll
        for (int kc = 0; kc < 8; kc++) {
            unsigned a[2][4];
            #pragma unroll
            for (int mf = 0; mf < 2; mf++) {
                a[mf][0] = __float_as_uint(Pw[(mf * 16 + lr    ) * PS + kc * 8 + lc    ]);
                a[mf][1] = __float_as_uint(Pw[(mf * 16 + lr + 8) * PS + kc * 8 + lc    ]);
                a[mf][2] = __float_as_uint(Pw[(mf * 16 + lr    ) * PS + kc * 8 + lc + 4]);
                a[mf][3] = __float_as_uint(Pw[(mf * 16 + lr + 8) * PS + kc * 8 + lc + 4]);
            }
            #pragma unroll
            for (int nc = 0; nc < 8; nc++) {
                float2 vb = *reinterpret_cast<const float2*>(&Vt[(kc * 64 + nc * 8 + lr) * 8 + 2 * lc]);
                unsigned b0 = __float_as_uint(vb.x), b1 = __float_as_uint(vb.y);
                mma_tf32(o[0][nc], a[0], b0, b1);
                mma_tf32(o[1][nc], a[1], b0, b1);
            }
        }
    }

    // finalize
    #pragma unroll
    for (int mf = 0; mf < 2; mf++) {
        float l0 = lrow[mf][0], l1 = lrow[mf][1];
        l0 += __shfl_xor_sync(0xffffffff, l0, 1);
        l0 += __shfl_xor_sync(0xffffffff, l0, 2);
        l1 += __shfl_xor_sync(0xffffffff, l1, 1);
        l1 += __shfl_xor_sync(0xffffffff, l1, 2);
        float inv0 = 1.f / l0;
        float inv1 = 1.f / l1;
        float* O0 = Ctx + (size_t)(q0 + w32 + mf * 16 + lr) * D_MODEL + h * D_HEAD;
        float* O1 = O0 + (size_t)8 * D_MODEL;
        #pragma unroll
        for (int nc = 0; nc < 8; nc++) {
            int col = nc * 8 + 2 * lc;
            float2 v0; v0.x = o[mf][nc][0] * inv0; v0.y = o[mf][nc][1] * inv0;
            float2 v1; v1.x = o[mf][nc][2] * inv1; v1.y = o[mf][nc][3] * inv1;
            *reinterpret_cast<float2*>(&O0[col]) = v0;
            *reinterpret_cast<float2*>(&O1[col]) = v1;
        }
    }
}

// ---------------- launch ----------------
extern "C" void kernel_launch(void* const* d_in, const int* in_sizes, int n_in,
                              void* d_out, int out_size) {
    const float* query = (const float*)d_in[0];
    const float* key   = (const float*)d_in[1];
    const float* value = (const float*)d_in[2];
    const int*   mask  = (const int*)d_in[3];
    const float* Wq = (const float*)d_in[4];
    const float* bq = (const float*)d_in[5];
    const float* Wk = (const float*)d_in[6];
    const float* bk = (const float*)d_in[7];
    const float* Wv = (const float*)d_in[8];
    const float* bv = (const float*)d_in[9];
    const float* Wo = (const float*)d_in[10];
    const float* bo = (const float*)d_in[11];
    float* out = (float*)d_out;

    void *pQ, *pK, *pV, *pC;
    cudaGetSymbolAddress(&pQ, g_Q);
    cudaGetSymbolAddress(&pK, g_K);
    cudaGetSymbolAddress(&pV, g_V);
    cudaGetSymbolAddress(&pC, g_CTX);

    const int fsmem = FSMEM_FLOATS * (int)sizeof(float);
    cudaFuncSetAttribute(flash_attn_mma, cudaFuncAttributeMaxDynamicSharedMemorySize, fsmem);

    dim3 gridP(D_MODEL / GBN, S_LEN / GBM);   // (12, 32)
    const float qscale = 1.0f / 8.0f;

    gemm_tf32<<<gridP, 128>>>(query, Wq, bq, (float*)pQ, S_LEN, D_MODEL, D_MODEL, qscale);
    gemm_tf32<<<gridP, 128>>>(key,   Wk, bk, (float*)pK, S_LEN, D_MODEL, D_MODEL, 1.0f);
    gemm_tf32<<<gridP, 128>>>(value, Wv, bv, (float*)pV, S_LEN, D_MODEL, D_MODEL, 1.0f);

    dim3 gridA(S_LEN / FBQ, N_HEADS);         // (32, 12)
    flash_attn_mma<<<gridA, 128, fsmem>>>((const float*)pQ, (const float*)pK,
                                          (const float*)pV, mask, (float*)pC);

    gemm_tf32<<<gridP, 128>>>((const float*)pC, Wo, bo, out, S_LEN, D_MODEL, D_MODEL, 1.0f);
}

// round 5
// speedup vs baseline: 1.3595x; 1.3595x over previous
#include <cuda_runtime.h>
#include <math.h>

#define S_LEN 4096
#define D_MODEL 768
#define N_HEADS 12
#define D_HEAD 64

// ---------------- scratch (no allocations allowed) ----------------
__device__ float g_Q[S_LEN * D_MODEL];
__device__ float g_K[S_LEN * D_MODEL];
__device__ float g_V[S_LEN * D_MODEL];
__device__ float g_CTX[S_LEN * D_MODEL];

// ---------------- tf32 helpers ----------------
__device__ __forceinline__ unsigned cvt_tf32(float f) {
    unsigned r;
    asm("cvt.rna.tf32.f32 %0, %1;" : "=r"(r) : "f"(f));
    return r;
}
__device__ __forceinline__ float cvt_tf32f(float f) {
    return __uint_as_float(cvt_tf32(f));
}
__device__ __forceinline__ void mma_tf32(float* c, const unsigned* a, unsigned b0, unsigned b1) {
    asm volatile(
        "mma.sync.aligned.m16n8k8.row.col.f32.tf32.tf32.f32 "
        "{%0,%1,%2,%3}, {%4,%5,%6,%7}, {%8,%9}, {%0,%1,%2,%3};\n"
        : "+f"(c[0]), "+f"(c[1]), "+f"(c[2]), "+f"(c[3])
        : "r"(a[0]), "r"(a[1]), "r"(a[2]), "r"(a[3]), "r"(b0), "r"(b1));
}

// pair-interleave position of column c within its 8-wide k-group:
// col lc (0..3) -> 2*lc, col lc+4 -> 2*lc+1
__device__ __forceinline__ int pairpos(int c8) { return 2 * (c8 & 3) + (c8 >> 2); }

// ============================================================================
// GEMM (tf32): C[M,N] = (A[M,K] @ B[N,K]^T + bias[N]) * scale
// 128 threads / 4 warps. BM=128 (warp M=32), BN=64, BK=32. (round-3 version,
// measured ~123us for all four projections)
// ============================================================================
#define GBM 128
#define GBN 64
#define GBK 32
#define GAS 40
#define GBS 40

__global__ __launch_bounds__(128)
void gemm_tf32(const float* __restrict__ A, const float* __restrict__ B,
               const float* __restrict__ bias, float* __restrict__ C,
               int M, int N, int K, float scale) {
    __shared__ float Ap[GBM * GAS];
    __shared__ float Bp[GBN * GBS];

    const int tid  = threadIdx.x;
    const int warp = tid >> 5;
    const int lane = tid & 31;
    const int lr = lane >> 2;
    const int lc = lane & 3;

    const int crow = blockIdx.y * GBM;
    const int ccol = blockIdx.x * GBN;

    float acc[2][8][4];
    #pragma unroll
    for (int mf = 0; mf < 2; mf++)
        #pragma unroll
        for (int nc = 0; nc < 8; nc++)
            #pragma unroll
            for (int i = 0; i < 4; i++) acc[mf][nc][i] = 0.f;

    for (int kt = 0; kt < K; kt += GBK) {
        #pragma unroll
        for (int it = 0; it < 8; it++) {
            int t = tid + it * 128;
            int row = t >> 3;
            int c4  = (t & 7) * 4;
            float4 a4 = *reinterpret_cast<const float4*>(&A[(size_t)(crow + row) * K + kt + c4]);
            int base = row * GAS + (c4 >> 3) * 8;
            Ap[base + pairpos((c4 + 0) & 7)] = cvt_tf32f(a4.x);
            Ap[base + pairpos((c4 + 1) & 7)] = cvt_tf32f(a4.y);
            Ap[base + pairpos((c4 + 2) & 7)] = cvt_tf32f(a4.z);
            Ap[base + pairpos((c4 + 3) & 7)] = cvt_tf32f(a4.w);
        }
        #pragma unroll
        for (int it = 0; it < 4; it++) {
            int t = tid + it * 128;
            int row = t >> 3;
            int c4  = (t & 7) * 4;
            float4 b4 = *reinterpret_cast<const float4*>(&B[(size_t)(ccol + row) * K + kt + c4]);
            int base = row * GBS + (c4 >> 3) * 8;
            Bp[base + pairpos((c4 + 0) & 7)] = cvt_tf32f(b4.x);
            Bp[base + pairpos((c4 + 1) & 7)] = cvt_tf32f(b4.y);
            Bp[base + pairpos((c4 + 2) & 7)] = cvt_tf32f(b4.z);
            Bp[base + pairpos((c4 + 3) & 7)] = cvt_tf32f(b4.w);
        }
        __syncthreads();

        #pragma unroll
        for (int kc = 0; kc < GBK / 8; kc++) {
            unsigned a[2][4];
            #pragma unroll
            for (int mf = 0; mf < 2; mf++) {
                int r0 = warp * 32 + mf * 16 + lr;
                float2 p0 = *reinterpret_cast<const float2*>(&Ap[(r0    ) * GAS + kc * 8 + 2 * lc]);
                float2 p1 = *reinterpret_cast<const float2*>(&Ap[(r0 + 8) * GAS + kc * 8 + 2 * lc]);
                a[mf][0] = __float_as_uint(p0.x); a[mf][2] = __float_as_uint(p0.y);
                a[mf][1] = __float_as_uint(p1.x); a[mf][3] = __float_as_uint(p1.y);
            }
            #pragma unroll
            for (int nc = 0; nc < 8; nc++) {
                float2 bp = *reinterpret_cast<const float2*>(&Bp[(nc * 8 + lr) * GBS + kc * 8 + 2 * lc]);
                unsigned b0 = __float_as_uint(bp.x), b1 = __float_as_uint(bp.y);
                mma_tf32(acc[0][nc], a[0], b0, b1);
                mma_tf32(acc[1][nc], a[1], b0, b1);
            }
        }
        __syncthreads();
    }

    #pragma unroll
    for (int mf = 0; mf < 2; mf++) {
        int row0 = crow + warp * 32 + mf * 16 + lr;
        #pragma unroll
        for (int nc = 0; nc < 8; nc++) {
            int col = ccol + nc * 8 + 2 * lc;
            float b0 = bias[col], b1 = bias[col + 1];
            float2 v0, v1;
            v0.x = (acc[mf][nc][0] + b0) * scale;
            v0.y = (acc[mf][nc][1] + b1) * scale;
            v1.x = (acc[mf][nc][2] + b0) * scale;
            v1.y = (acc[mf][nc][3] + b1) * scale;
            *reinterpret_cast<float2*>(&C[(size_t)row0 * N + col])       = v0;
            *reinterpret_cast<float2*>(&C[(size_t)(row0 + 8) * N + col]) = v1;
        }
    }
}

// ============================================================================
// Flash attention (tf32). Round-2 skeleton: 128 threads / 4 warps, warp M=16,
// BQ=64, Q fragments in registers. New: P smem round-trip replaced by
// shfl-based C->A fragment conversion; K staged pair-interleaved for float2
// B-fragment loads. Smem 37KB (static), no Psh.
// ============================================================================
#define FBQ 64
#define FBK 64
#define KS 72
#define VS 72

__global__ __launch_bounds__(128)
void flash_attn_mma(const float* __restrict__ Q, const float* __restrict__ K,
                    const float* __restrict__ V, const int* __restrict__ mask,
                    float* __restrict__ Ctx) {
    __shared__ float Ksh[64 * KS];   // pair-interleaved along k
    __shared__ float Vsh[64 * VS];   // plain [key][d] (scalar b-frag reads conflict-free)
    __shared__ float msk[64];

    const int h  = blockIdx.y;
    const int q0 = blockIdx.x * FBQ;
    const int tid  = threadIdx.x;
    const int warp = tid >> 5;
    const int lane = tid & 31;
    const int lr = lane >> 2;
    const int lc = lane & 3;

    // shfl source lanes for C->A fragment conversion
    const int srcA = (lane & ~3) | (lc >> 1);   // row group, col lc
    const int srcB = srcA + 2;                  // col lc+4
    const bool oddc = (lc & 1);

    // Q fragments (16 rows per warp) in registers, tf32-rounded
    unsigned aq[8][4];
    const float* Qb = Q + (size_t)(q0 + warp * 16) * D_MODEL + h * D_HEAD;
    #pragma unroll
    for (int kc = 0; kc < 8; kc++) {
        aq[kc][0] = cvt_tf32(Qb[(size_t)(lr    ) * D_MODEL + kc * 8 + lc    ]);
        aq[kc][1] = cvt_tf32(Qb[(size_t)(lr + 8) * D_MODEL + kc * 8 + lc    ]);
        aq[kc][2] = cvt_tf32(Qb[(size_t)(lr    ) * D_MODEL + kc * 8 + lc + 4]);
        aq[kc][3] = cvt_tf32(Qb[(size_t)(lr + 8) * D_MODEL + kc * 8 + lc + 4]);
    }

    float o[8][4];
    #pragma unroll
    for (int nc = 0; nc < 8; nc++)
        #pragma unroll
        for (int i = 0; i < 4; i++) o[nc][i] = 0.f;
    float m0 = -1e30f, m1 = -1e30f, l0 = 0.f, l1 = 0.f;

    for (int kt = 0; kt < S_LEN; kt += FBK) {
        __syncthreads();
        // stage K (pair-interleaved) and V (plain), tf32-rounded
        #pragma unroll
        for (int it = 0; it < 8; it++) {
            int t = tid + it * 128;
            int row = t >> 4;
            int c4  = (t & 15) * 4;
            const float* kp = K + (size_t)(kt + row) * D_MODEL + h * D_HEAD + c4;
            const float* vp = V + (size_t)(kt + row) * D_MODEL + h * D_HEAD + c4;
            float4 k4 = *reinterpret_cast<const float4*>(kp);
            float4 v4 = *reinterpret_cast<const float4*>(vp);
            int kb = row * KS + (c4 >> 3) * 8;
            Ksh[kb + pairpos((c4 + 0) & 7)] = cvt_tf32f(k4.x);
            Ksh[kb + pairpos((c4 + 1) & 7)] = cvt_tf32f(k4.y);
            Ksh[kb + pairpos((c4 + 2) & 7)] = cvt_tf32f(k4.z);
            Ksh[kb + pairpos((c4 + 3) & 7)] = cvt_tf32f(k4.w);
            int vb = row * VS + c4;
            Vsh[vb + 0] = cvt_tf32f(v4.x);
            Vsh[vb + 1] = cvt_tf32f(v4.y);
            Vsh[vb + 2] = cvt_tf32f(v4.z);
            Vsh[vb + 3] = cvt_tf32f(v4.w);
        }
        if (tid < FBK) msk[tid] = (mask[kt + tid] != 0) ? 0.f : -1e30f;
        __syncthreads();

        // S = Q @ K^T (16 x 64 per warp)
        float cs[8][4];
        #pragma unroll
        for (int nc = 0; nc < 8; nc++)
            #pragma unroll
            for (int i = 0; i < 4; i++) cs[nc][i] = 0.f;
        #pragma unroll
        for (int kc = 0; kc < 8; kc++) {
            #pragma unroll
            for (int nc = 0; nc < 8; nc++) {
                float2 kb = *reinterpret_cast<const float2*>(&Ksh[(nc * 8 + lr) * KS + kc * 8 + 2 * lc]);
                unsigned b0 = __float_as_uint(kb.x), b1 = __float_as_uint(kb.y);
                mma_tf32(cs[nc], aq[kc], b0, b1);
            }
        }

        // mask add
        #pragma unroll
        for (int nc = 0; nc < 8; nc++) {
            float mk0 = msk[nc * 8 + 2 * lc];
            float mk1 = msk[nc * 8 + 2 * lc + 1];
            cs[nc][0] += mk0; cs[nc][1] += mk1;
            cs[nc][2] += mk0; cs[nc][3] += mk1;
        }

        // online softmax
        float mx0 = -1e30f, mx1 = -1e30f;
        #pragma unroll
        for (int nc = 0; nc < 8; nc++) {
            mx0 = fmaxf(mx0, fmaxf(cs[nc][0], cs[nc][1]));
            mx1 = fmaxf(mx1, fmaxf(cs[nc][2], cs[nc][3]));
        }
        mx0 = fmaxf(mx0, __shfl_xor_sync(0xffffffff, mx0, 1));
        mx0 = fmaxf(mx0, __shfl_xor_sync(0xffffffff, mx0, 2));
        mx1 = fmaxf(mx1, __shfl_xor_sync(0xffffffff, mx1, 1));
        mx1 = fmaxf(mx1, __shfl_xor_sync(0xffffffff, mx1, 2));

        float m0n = fmaxf(m0, mx0);
        float m1n = fmaxf(m1, mx1);
        float corr0 = __expf(m0 - m0n);
        float corr1 = __expf(m1 - m1n);
        m0 = m0n; m1 = m1n;
        l0 *= corr0; l1 *= corr1;
        #pragma unroll
        for (int nc = 0; nc < 8; nc++) {
            o[nc][0] *= corr0; o[nc][1] *= corr0;
            o[nc][2] *= corr1; o[nc][3] *= corr1;
        }

        // P = exp(S - m): accumulate l, overwrite cs with tf32 P (C-layout)
        #pragma unroll
        for (int nc = 0; nc < 8; nc++) {
            float p0 = __expf(cs[nc][0] - m0);
            float p1 = __expf(cs[nc][1] - m0);
            float p2 = __expf(cs[nc][2] - m1);
            float p3 = __expf(cs[nc][3] - m1);
            l0 += p0 + p1;
            l1 += p2 + p3;
            cs[nc][0] = cvt_tf32f(p0);
            cs[nc][1] = cvt_tf32f(p1);
            cs[nc][2] = cvt_tf32f(p2);
            cs[nc][3] = cvt_tf32f(p3);
        }

        // O += P @ V : A-fragments built from cs via shfl (no smem)
        #pragma unroll
        for (int kc = 0; kc < 8; kc++) {
            float s0 = __shfl_sync(0xffffffffu, cs[kc][0], srcA);
            float s1 = __shfl_sync(0xffffffffu, cs[kc][1], srcA);
            float s2 = __shfl_sync(0xffffffffu, cs[kc][2], srcA);
            float s3 = __shfl_sync(0xffffffffu, cs[kc][3], srcA);
            float t0 = __shfl_sync(0xffffffffu, cs[kc][0], srcB);
            float t1 = __shfl_sync(0xffffffffu, cs[kc][1], srcB);
            float t2 = __shfl_sync(0xffffffffu, cs[kc][2], srcB);
            float t3 = __shfl_sync(0xffffffffu, cs[kc][3], srcB);
            unsigned a[4];
            a[0] = __float_as_uint(oddc ? s1 : s0);   // (lr,   lc)
            a[1] = __float_as_uint(oddc ? s3 : s2);   // (lr+8, lc)
            a[2] = __float_as_uint(oddc ? t1 : t0);   // (lr,   lc+4)
            a[3] = __float_as_uint(oddc ? t3 : t2);   // (lr+8, lc+4)
            #pragma unroll
            for (int nc = 0; nc < 8; nc++) {
                unsigned b0 = __float_as_uint(Vsh[(kc * 8 + lc    ) * VS + nc * 8 + lr]);
                unsigned b1 = __float_as_uint(Vsh[(kc * 8 + lc + 4) * VS + nc * 8 + lr]);
                mma_tf32(o[nc], a, b0, b1);
            }
        }
    }

    // finalize
    l0 += __shfl_xor_sync(0xffffffff, l0, 1);
    l0 += __shfl_xor_sync(0xffffffff, l0, 2);
    l1 += __shfl_xor_sync(0xffffffff, l1, 1);
    l1 += __shfl_xor_sync(0xffffffff, l1, 2);
    float inv0 = 1.f / l0;
    float inv1 = 1.f / l1;

    float* O0 = Ctx + (size_t)(q0 + warp * 16 + lr) * D_MODEL + h * D_HEAD;
    float* O1 = O0 + (size_t)8 * D_MODEL;
    #pragma unroll
    for (int nc = 0; nc < 8; nc++) {
        int col = nc * 8 + 2 * lc;
        float2 v0; v0.x = o[nc][0] * inv0; v0.y = o[nc][1] * inv0;
        float2 v1; v1.x = o[nc][2] * inv1; v1.y = o[nc][3] * inv1;
        *reinterpret_cast<float2*>(&O0[col]) = v0;
        *reinterpret_cast<float2*>(&O1[col]) = v1;
    }
}

// ---------------- launch ----------------
extern "C" void kernel_launch(void* const* d_in, const int* in_sizes, int n_in,
                              void* d_out, int out_size) {
    const float* query = (const float*)d_in[0];
    const float* key   = (const float*)d_in[1];
    const float* value = (const float*)d_in[2];
    const int*   mask  = (const int*)d_in[3];
    const float* Wq = (const float*)d_in[4];
    const float* bq = (const float*)d_in[5];
    const float* Wk = (const float*)d_in[6];
    const float* bk = (const float*)d_in[7];
    const float* Wv = (const float*)d_in[8];
    const float* bv = (const float*)d_in[9];
    const float* Wo = (const float*)d_in[10];
    const float* bo = (const float*)d_in[11];
    float* out = (float*)d_out;

    void *pQ, *pK, *pV, *pC;
    cudaGetSymbolAddress(&pQ, g_Q);
    cudaGetSymbolAddress(&pK, g_K);
    cudaGetSymbolAddress(&pV, g_V);
    cudaGetSymbolAddress(&pC, g_CTX);

    dim3 gridP(D_MODEL / GBN, S_LEN / GBM);   // (12, 32)
    const float qscale = 1.0f / 8.0f;

    gemm_tf32<<<gridP, 128>>>(query, Wq, bq, (float*)pQ, S_LEN, D_MODEL, D_MODEL, qscale);
    gemm_tf32<<<gridP, 128>>>(key,   Wk, bk, (float*)pK, S_LEN, D_MODEL, D_MODEL, 1.0f);
    gemm_tf32<<<gridP, 128>>>(value, Wv, bv, (float*)pV, S_LEN, D_MODEL, D_MODEL, 1.0f);

    dim3 gridA(S_LEN / FBQ, N_HEADS);         // (64, 12)
    flash_attn_mma<<<gridA, 128>>>((const float*)pQ, (const float*)pK,
                                   (const float*)pV, mask, (float*)pC);

    gemm_tf32<<<gridP, 128>>>((const float*)pC, Wo, bo, out, S_LEN, D_MODEL, D_MODEL, 1.0f);
}

// round 7
// speedup vs baseline: 2.7508x; 2.0234x over previous
#include <cuda_runtime.h>
#include <cuda_fp16.h>
#include <math.h>
#include <stdint.h>

#define S_LEN 4096
#define D_MODEL 768
#define N_HEADS 12
#define D_HEAD 64

// ---------------- scratch (no allocations allowed) ----------------
__device__ float g_Q[S_LEN * D_MODEL];
__device__ float g_K[S_LEN * D_MODEL];
__device__ float g_V[S_LEN * D_MODEL];
__device__ float g_CTX[S_LEN * D_MODEL];

// ---------------- tf32 helpers (projection GEMM, unchanged) ----------------
__device__ __forceinline__ unsigned cvt_tf32(float f) {
    unsigned r;
    asm("cvt.rna.tf32.f32 %0, %1;" : "=r"(r) : "f"(f));
    return r;
}
__device__ __forceinline__ float cvt_tf32f(float f) {
    return __uint_as_float(cvt_tf32(f));
}
__device__ __forceinline__ void mma_tf32(float* c, const unsigned* a, unsigned b0, unsigned b1) {
    asm volatile(
        "mma.sync.aligned.m16n8k8.row.col.f32.tf32.tf32.f32 "
        "{%0,%1,%2,%3}, {%4,%5,%6,%7}, {%8,%9}, {%0,%1,%2,%3};\n"
        : "+f"(c[0]), "+f"(c[1]), "+f"(c[2]), "+f"(c[3])
        : "r"(a[0]), "r"(a[1]), "r"(a[2]), "r"(a[3]), "r"(b0), "r"(b1));
}
__device__ __forceinline__ int pairpos(int c8) { return 2 * (c8 & 3) + (c8 >> 2); }

// ---------------- fp16 helpers (flash) ----------------
__device__ __forceinline__ void mma_f16(float* c, const unsigned* a, unsigned b0, unsigned b1) {
    asm volatile(
        "mma.sync.aligned.m16n8k16.row.col.f32.f16.f16.f32 "
        "{%0,%1,%2,%3}, {%4,%5,%6,%7}, {%8,%9}, {%0,%1,%2,%3};\n"
        : "+f"(c[0]), "+f"(c[1]), "+f"(c[2]), "+f"(c[3])
        : "r"(a[0]), "r"(a[1]), "r"(a[2]), "r"(a[3]), "r"(b0), "r"(b1));
}
__device__ __forceinline__ uint32_t smem_u32(const void* p) {
    uint32_t a;
    asm("{ .reg .u64 t; cvta.to.shared.u64 t, %1; cvt.u32.u64 %0, t; }" : "=r"(a) : "l"(p));
    return a;
}
__device__ __forceinline__ void ldsm_x2(unsigned& r0, unsigned& r1, uint32_t addr) {
    asm volatile("ldmatrix.sync.aligned.m8n8.x2.shared.b16 {%0,%1}, [%2];"
                 : "=r"(r0), "=r"(r1) : "r"(addr));
}
__device__ __forceinline__ void ldsm_x2_t(unsigned& r0, unsigned& r1, uint32_t addr) {
    asm volatile("ldmatrix.sync.aligned.m8n8.x2.trans.shared.b16 {%0,%1}, [%2];"
                 : "=r"(r0), "=r"(r1) : "r"(addr));
}
__device__ __forceinline__ void ldsm_x4(unsigned* r, uint32_t addr) {
    asm volatile("ldmatrix.sync.aligned.m8n8.x4.shared.b16 {%0,%1,%2,%3}, [%4];"
                 : "=r"(r[0]), "=r"(r[1]), "=r"(r[2]), "=r"(r[3]) : "r"(addr));
}
__device__ __forceinline__ unsigned h2u(float x, float y) {
    __half2 h = __floats2half2_rn(x, y);
    return *reinterpret_cast<unsigned*>(&h);
}

// ============================================================================
// GEMM (tf32 warp-mma): unchanged round-3 version (~123us for 4 projections)
// ============================================================================
#define GBM 128
#define GBN 64
#define GBK 32
#define GAS 40
#define GBS 40

__global__ __launch_bounds__(128)
void gemm_tf32(const float* __restrict__ A, const float* __restrict__ B,
               const float* __restrict__ bias, float* __restrict__ C,
               int M, int N, int K, float scale) {
    __shared__ float Ap[GBM * GAS];
    __shared__ float Bp[GBN * GBS];

    const int tid  = threadIdx.x;
    const int warp = tid >> 5;
    const int lane = tid & 31;
    const int lr = lane >> 2;
    const int lc = lane & 3;

    const int crow = blockIdx.y * GBM;
    const int ccol = blockIdx.x * GBN;

    float acc[2][8][4];
    #pragma unroll
    for (int mf = 0; mf < 2; mf++)
        #pragma unroll
        for (int nc = 0; nc < 8; nc++)
            #pragma unroll
            for (int i = 0; i < 4; i++) acc[mf][nc][i] = 0.f;

    for (int kt = 0; kt < K; kt += GBK) {
        #pragma unroll
        for (int it = 0; it < 8; it++) {
            int t = tid + it * 128;
            int row = t >> 3;
            int c4  = (t & 7) * 4;
            float4 a4 = *reinterpret_cast<const float4*>(&A[(size_t)(crow + row) * K + kt + c4]);
            int base = row * GAS + (c4 >> 3) * 8;
            Ap[base + pairpos((c4 + 0) & 7)] = cvt_tf32f(a4.x);
            Ap[base + pairpos((c4 + 1) & 7)] = cvt_tf32f(a4.y);
            Ap[base + pairpos((c4 + 2) & 7)] = cvt_tf32f(a4.z);
            Ap[base + pairpos((c4 + 3) & 7)] = cvt_tf32f(a4.w);
        }
        #pragma unroll
        for (int it = 0; it < 4; it++) {
            int t = tid + it * 128;
            int row = t >> 3;
            int c4  = (t & 7) * 4;
            float4 b4 = *reinterpret_cast<const float4*>(&B[(size_t)(ccol + row) * K + kt + c4]);
            int base = row * GBS + (c4 >> 3) * 8;
            Bp[base + pairpos((c4 + 0) & 7)] = cvt_tf32f(b4.x);
            Bp[base + pairpos((c4 + 1) & 7)] = cvt_tf32f(b4.y);
            Bp[base + pairpos((c4 + 2) & 7)] = cvt_tf32f(b4.z);
            Bp[base + pairpos((c4 + 3) & 7)] = cvt_tf32f(b4.w);
        }
        __syncthreads();

        #pragma unroll
        for (int kc = 0; kc < GBK / 8; kc++) {
            unsigned a[2][4];
            #pragma unroll
            for (int mf = 0; mf < 2; mf++) {
                int r0 = warp * 32 + mf * 16 + lr;
                float2 p0 = *reinterpret_cast<const float2*>(&Ap[(r0    ) * GAS + kc * 8 + 2 * lc]);
                float2 p1 = *reinterpret_cast<const float2*>(&Ap[(r0 + 8) * GAS + kc * 8 + 2 * lc]);
                a[mf][0] = __float_as_uint(p0.x); a[mf][2] = __float_as_uint(p0.y);
                a[mf][1] = __float_as_uint(p1.x); a[mf][3] = __float_as_uint(p1.y);
            }
            #pragma unroll
            for (int nc = 0; nc < 8; nc++) {
                float2 bp = *reinterpret_cast<const float2*>(&Bp[(nc * 8 + lr) * GBS + kc * 8 + 2 * lc]);
                unsigned b0 = __float_as_uint(bp.x), b1 = __float_as_uint(bp.y);
                mma_tf32(acc[0][nc], a[0], b0, b1);
                mma_tf32(acc[1][nc], a[1], b0, b1);
            }
        }
        __syncthreads();
    }

    #pragma unroll
    for (int mf = 0; mf < 2; mf++) {
        int row0 = crow + warp * 32 + mf * 16 + lr;
        #pragma unroll
        for (int nc = 0; nc < 8; nc++) {
            int col = ccol + nc * 8 + 2 * lc;
            float b0 = bias[col], b1 = bias[col + 1];
            float2 v0, v1;
            v0.x = (acc[mf][nc][0] + b0) * scale;
            v0.y = (acc[mf][nc][1] + b1) * scale;
            v1.x = (acc[mf][nc][2] + b0) * scale;
            v1.y = (acc[mf][nc][3] + b1) * scale;
            *reinterpret_cast<float2*>(&C[(size_t)row0 * N + col])       = v0;
            *reinterpret_cast<float2*>(&C[(size_t)(row0 + 8) * N + col]) = v1;
        }
    }
}

// ============================================================================
// Flash attention, fp16 mma (m16n8k16) + ldmatrix.
// 128 threads / 4 warps, warp M=16 -> BQ=64, key tiles FBK=64.
// K/V staged fp16 [row][72]; P per-warp fp16 [16][72]. All fragment loads via
// ldmatrix (HW conflict-free); fp32 softmax identical to round 2.
// ============================================================================
#define FBQ 64
#define FBK 64
#define HS 72    // half stride per row

__global__ __launch_bounds__(128)
void flash_f16(const float* __restrict__ Q, const float* __restrict__ K,
               const float* __restrict__ V, const int* __restrict__ mask,
               float* __restrict__ Ctx) {
    __shared__ __half Ksh[64 * HS];
    __shared__ __half Vsh[64 * HS];
    __shared__ __half Psh[4 * 16 * HS];
    __shared__ float  msk[64];

    const int h  = blockIdx.y;
    const int q0 = blockIdx.x * FBQ;
    const int tid  = threadIdx.x;
    const int warp = tid >> 5;
    const int lane = tid & 31;
    const int lr = lane >> 2;
    const int lc = lane & 3;

    const uint32_t Kb = smem_u32(Ksh);
    const uint32_t Vb = smem_u32(Vsh);
    const uint32_t Pb = smem_u32(Psh);

    // ldmatrix lane-address components
    const int l7  = lane & 7;
    const int l15 = lane & 15;
    const int sel = (lane >> 3) & 1;          // x2: matrix select
    const int s4  = (lane >> 3) & 3;          // x4: matrix select

    // Q fragments in registers (fp16): 4 kc-groups x 4 half2
    unsigned aq[4][4];
    {
        const float* Qp = Q + (size_t)(q0 + warp * 16) * D_MODEL + h * D_HEAD;
        #pragma unroll
        for (int kc = 0; kc < 4; kc++) {
            float2 x0 = *reinterpret_cast<const float2*>(&Qp[(size_t)(lr    ) * D_MODEL + kc * 16 + 2 * lc    ]);
            float2 x1 = *reinterpret_cast<const float2*>(&Qp[(size_t)(lr + 8) * D_MODEL + kc * 16 + 2 * lc    ]);
            float2 x2 = *reinterpret_cast<const float2*>(&Qp[(size_t)(lr    ) * D_MODEL + kc * 16 + 2 * lc + 8]);
            float2 x3 = *reinterpret_cast<const float2*>(&Qp[(size_t)(lr + 8) * D_MODEL + kc * 16 + 2 * lc + 8]);
            aq[kc][0] = h2u(x0.x, x0.y);
            aq[kc][1] = h2u(x1.x, x1.y);
            aq[kc][2] = h2u(x2.x, x2.y);
            aq[kc][3] = h2u(x3.x, x3.y);
        }
    }

    float o[8][4];
    #pragma unroll
    for (int nc = 0; nc < 8; nc++)
        #pragma unroll
        for (int i = 0; i < 4; i++) o[nc][i] = 0.f;
    float m0 = -1e30f, m1 = -1e30f, l0 = 0.f, l1 = 0.f;

    for (int kt = 0; kt < S_LEN; kt += FBK) {
        __syncthreads();
        // stage K and V tiles as fp16 [row][HS]
        #pragma unroll
        for (int it = 0; it < 4; it++) {
            int t = tid + it * 128;            // 0..511
            int row = t >> 3;                   // 0..63
            int c8  = (t & 7) * 8;              // 0..56
            const float* kp = K + (size_t)(kt + row) * D_MODEL + h * D_HEAD + c8;
            const float* vp = V + (size_t)(kt + row) * D_MODEL + h * D_HEAD + c8;
            float4 ka = *reinterpret_cast<const float4*>(kp);
            float4 kbv = *reinterpret_cast<const float4*>(kp + 4);
            float4 va = *reinterpret_cast<const float4*>(vp);
            float4 vb = *reinterpret_cast<const float4*>(vp + 4);
            unsigned* kd = reinterpret_cast<unsigned*>(&Ksh[row * HS + c8]);
            unsigned* vd = reinterpret_cast<unsigned*>(&Vsh[row * HS + c8]);
            kd[0] = h2u(ka.x, ka.y); kd[1] = h2u(ka.z, ka.w);
            kd[2] = h2u(kbv.x, kbv.y); kd[3] = h2u(kbv.z, kbv.w);
            vd[0] = h2u(va.x, va.y); vd[1] = h2u(va.z, va.w);
            vd[2] = h2u(vb.x, vb.y); vd[3] = h2u(vb.z, vb.w);
        }
        if (tid < FBK) msk[tid] = (mask[kt + tid] != 0) ? 0.f : -1e30f;
        __syncthreads();

        // S = Q @ K^T : B-frags via ldmatrix.x2 on K rows
        float cs[8][4];
        #pragma unroll
        for (int nc = 0; nc < 8; nc++)
            #pragma unroll
            for (int i = 0; i < 4; i++) cs[nc][i] = 0.f;
        #pragma unroll
        for (int kc = 0; kc < 4; kc++) {
            #pragma unroll
            for (int nc = 0; nc < 8; nc++) {
                unsigned b0, b1;
                uint32_t addr = Kb + 2u * ((nc * 8 + l7) * HS + kc * 16 + sel * 8);
                ldsm_x2(b0, b1, addr);
                mma_f16(cs[nc], aq[kc], b0, b1);
            }
        }

        // mask add
        #pragma unroll
        for (int nc = 0; nc < 8; nc++) {
            float mk0 = msk[nc * 8 + 2 * lc];
            float mk1 = msk[nc * 8 + 2 * lc + 1];
            cs[nc][0] += mk0; cs[nc][1] += mk1;
            cs[nc][2] += mk0; cs[nc][3] += mk1;
        }

        // online softmax (fp32)
        float mx0 = -1e30f, mx1 = -1e30f;
        #pragma unroll
        for (int nc = 0; nc < 8; nc++) {
            mx0 = fmaxf(mx0, fmaxf(cs[nc][0], cs[nc][1]));
            mx1 = fmaxf(mx1, fmaxf(cs[nc][2], cs[nc][3]));
        }
        mx0 = fmaxf(mx0, __shfl_xor_sync(0xffffffff, mx0, 1));
        mx0 = fmaxf(mx0, __shfl_xor_sync(0xffffffff, mx0, 2));
        mx1 = fmaxf(mx1, __shfl_xor_sync(0xffffffff, mx1, 1));
        mx1 = fmaxf(mx1, __shfl_xor_sync(0xffffffff, mx1, 2));

        float m0n = fmaxf(m0, mx0);
        float m1n = fmaxf(m1, mx1);
        float corr0 = __expf(m0 - m0n);
        float corr1 = __expf(m1 - m1n);
        m0 = m0n; m1 = m1n;
        l0 *= corr0; l1 *= corr1;
        #pragma unroll
        for (int nc = 0; nc < 8; nc++) {
            o[nc][0] *= corr0; o[nc][1] *= corr0;
            o[nc][2] *= corr1; o[nc][3] *= corr1;
        }

        // P = exp(S - m) -> fp16 to per-warp smem tile (C-layout half2 stores)
        __half* Pw = Psh + warp * 16 * HS;
        #pragma unroll
        for (int nc = 0; nc < 8; nc++) {
            float p0 = __expf(cs[nc][0] - m0);
            float p1 = __expf(cs[nc][1] - m0);
            float p2 = __expf(cs[nc][2] - m1);
            float p3 = __expf(cs[nc][3] - m1);
            l0 += p0 + p1;
            l1 += p2 + p3;
            *reinterpret_cast<unsigned*>(&Pw[(lr    ) * HS + nc * 8 + 2 * lc]) = h2u(p0, p1);
            *reinterpret_cast<unsigned*>(&Pw[(lr + 8) * HS + nc * 8 + 2 * lc]) = h2u(p2, p3);
        }
        __syncwarp();

        // O += P @ V : A-frags via ldmatrix.x4 on P, B-frags via ldmatrix.x2.trans on V
        #pragma unroll
        for (int kc = 0; kc < 4; kc++) {
            unsigned a[4];
            {
                int row = warp * 16 + l7 + (s4 & 1) * 8;
                int col = kc * 16 + (s4 >> 1) * 8;
                ldsm_x4(a, Pb + 2u * (row * HS + col));
            }
            #pragma unroll
            for (int nc = 0; nc < 8; nc++) {
                unsigned b0, b1;
                uint32_t addr = Vb + 2u * ((kc * 16 + l15) * HS + nc * 8);
                ldsm_x2_t(b0, b1, addr);
                mma_f16(o[nc], a, b0, b1);
            }
        }
    }

    // finalize
    l0 += __shfl_xor_sync(0xffffffff, l0, 1);
    l0 += __shfl_xor_sync(0xffffffff, l0, 2);
    l1 += __shfl_xor_sync(0xffffffff, l1, 1);
    l1 += __shfl_xor_sync(0xffffffff, l1, 2);
    float inv0 = 1.f / l0;
    float inv1 = 1.f / l1;

    float* O0 = Ctx + (size_t)(q0 + warp * 16 + lr) * D_MODEL + h * D_HEAD;
    float* O1 = O0 + (size_t)8 * D_MODEL;
    #pragma unroll
    for (int nc = 0; nc < 8; nc++) {
        int col = nc * 8 + 2 * lc;
        float2 v0; v0.x = o[nc][0] * inv0; v0.y = o[nc][1] * inv0;
        float2 v1; v1.x = o[nc][2] * inv1; v1.y = o[nc][3] * inv1;
        *reinterpret_cast<float2*>(&O0[col]) = v0;
        *reinterpret_cast<float2*>(&O1[col]) = v1;
    }
}

// ---------------- launch ----------------
extern "C" void kernel_launch(void* const* d_in, const int* in_sizes, int n_in,
                              void* d_out, int out_size) {
    const float* query = (const float*)d_in[0];
    const float* key   = (const float*)d_in[1];
    const float* value = (const float*)d_in[2];
    const int*   mask  = (const int*)d_in[3];
    const float* Wq = (const float*)d_in[4];
    const float* bq = (const float*)d_in[5];
    const float* Wk = (const float*)d_in[6];
    const float* bk = (const float*)d_in[7];
    const float* Wv = (const float*)d_in[8];
    const float* bv = (const float*)d_in[9];
    const float* Wo = (const float*)d_in[10];
    const float* bo = (const float*)d_in[11];
    float* out = (float*)d_out;

    void *pQ, *pK, *pV, *pC;
    cudaGetSymbolAddress(&pQ, g_Q);
    cudaGetSymbolAddress(&pK, g_K);
    cudaGetSymbolAddress(&pV, g_V);
    cudaGetSymbolAddress(&pC, g_CTX);

    dim3 gridP(D_MODEL / GBN, S_LEN / GBM);   // (12, 32)
    const float qscale = 1.0f / 8.0f;

    gemm_tf32<<<gridP, 128>>>(query, Wq, bq, (float*)pQ, S_LEN, D_MODEL, D_MODEL, qscale);
    gemm_tf32<<<gridP, 128>>>(key,   Wk, bk, (float*)pK, S_LEN, D_MODEL, D_MODEL, 1.0f);
    gemm_tf32<<<gridP, 128>>>(value, Wv, bv, (float*)pV, S_LEN, D_MODEL, D_MODEL, 1.0f);

    dim3 gridA(S_LEN / FBQ, N_HEADS);         // (64, 12)
    flash_f16<<<gridA, 128>>>((const float*)pQ, (const float*)pK,
                              (const float*)pV, mask, (float*)pC);

    gemm_tf32<<<gridP, 128>>>((const float*)pC, Wo, bo, out, S_LEN, D_MODEL, D_MODEL, 1.0f);
}

// round 8
// speedup vs baseline: 3.2659x; 1.1872x over previous
#include <cuda_runtime.h>
#include <cuda_fp16.h>
#include <math.h>
#include <stdint.h>

#define S_LEN 4096
#define D_MODEL 768
#define N_HEADS 12
#define D_HEAD 64

// ---------------- scratch (no allocations allowed) ----------------
__device__ float g_Q[S_LEN * D_MODEL];
__device__ float g_K[S_LEN * D_MODEL];
__device__ float g_V[S_LEN * D_MODEL];
__device__ float g_CTX[S_LEN * D_MODEL];

// ---------------- fp16 helpers ----------------
__device__ __forceinline__ void mma_f16(float* c, const unsigned* a, unsigned b0, unsigned b1) {
    asm volatile(
        "mma.sync.aligned.m16n8k16.row.col.f32.f16.f16.f32 "
        "{%0,%1,%2,%3}, {%4,%5,%6,%7}, {%8,%9}, {%0,%1,%2,%3};\n"
        : "+f"(c[0]), "+f"(c[1]), "+f"(c[2]), "+f"(c[3])
        : "r"(a[0]), "r"(a[1]), "r"(a[2]), "r"(a[3]), "r"(b0), "r"(b1));
}
__device__ __forceinline__ uint32_t smem_u32(const void* p) {
    uint32_t a;
    asm("{ .reg .u64 t; cvta.to.shared.u64 t, %1; cvt.u32.u64 %0, t; }" : "=r"(a) : "l"(p));
    return a;
}
__device__ __forceinline__ void ldsm_x4(unsigned* r, uint32_t addr) {
    asm volatile("ldmatrix.sync.aligned.m8n8.x4.shared.b16 {%0,%1,%2,%3}, [%4];"
                 : "=r"(r[0]), "=r"(r[1]), "=r"(r[2]), "=r"(r[3]) : "r"(addr));
}
__device__ __forceinline__ void ldsm_x4_t(unsigned* r, uint32_t addr) {
    asm volatile("ldmatrix.sync.aligned.m8n8.x4.trans.shared.b16 {%0,%1,%2,%3}, [%4];"
                 : "=r"(r[0]), "=r"(r[1]), "=r"(r[2]), "=r"(r[3]) : "r"(addr));
}
__device__ __forceinline__ unsigned h2u(float x, float y) {
    __half2 h = __floats2half2_rn(x, y);
    return *reinterpret_cast<unsigned*>(&h);
}

// ============================================================================
// GEMM (fp16 mma m16n8k16 + ldmatrix): C = (A[M,K] @ B[N,K]^T + bias) * scale
// 128 threads / 4 warps. BM=128 (warp M=32), BN=64, BK=32. fp32 accumulate.
// ============================================================================
#define GBM 128
#define GBN 64
#define GBK 32
#define HSG 40   // half stride per staged row (32 data + 8 pad)

__global__ __launch_bounds__(128)
void gemm_f16(const float* __restrict__ A, const float* __restrict__ B,
              const float* __restrict__ bias, float* __restrict__ C,
              int M, int N, int K, float scale) {
    __shared__ __half Ash[GBM * HSG];
    __shared__ __half Bsh[GBN * HSG];

    const int tid  = threadIdx.x;
    const int warp = tid >> 5;
    const int lane = tid & 31;
    const int lr = lane >> 2;
    const int lc = lane & 3;
    const int l7 = lane & 7;
    const int se1 = (lane >> 3) & 1;   // low matrix-select bit
    const int se2 = (lane >> 4) & 1;   // high matrix-select bit

    const uint32_t Ab = smem_u32(Ash);
    const uint32_t Bb = smem_u32(Bsh);

    const int crow = blockIdx.y * GBM;
    const int ccol = blockIdx.x * GBN;

    float acc[2][8][4];
    #pragma unroll
    for (int mf = 0; mf < 2; mf++)
        #pragma unroll
        for (int nc = 0; nc < 8; nc++)
            #pragma unroll
            for (int i = 0; i < 4; i++) acc[mf][nc][i] = 0.f;

    for (int kt = 0; kt < K; kt += GBK) {
        // stage A (128x32 halfs)
        #pragma unroll
        for (int it = 0; it < 4; it++) {
            int t = tid + it * 128;            // 0..511
            int row = t >> 2;                   // 0..127
            int c8  = (t & 3) * 8;              // 0,8,16,24
            const float* ap = &A[(size_t)(crow + row) * K + kt + c8];
            float4 a0 = *reinterpret_cast<const float4*>(ap);
            float4 a1 = *reinterpret_cast<const float4*>(ap + 4);
            unsigned* d = reinterpret_cast<unsigned*>(&Ash[row * HSG + c8]);
            d[0] = h2u(a0.x, a0.y); d[1] = h2u(a0.z, a0.w);
            d[2] = h2u(a1.x, a1.y); d[3] = h2u(a1.z, a1.w);
        }
        // stage B (64x32 halfs)
        #pragma unroll
        for (int it = 0; it < 2; it++) {
            int t = tid + it * 128;            // 0..255
            int row = t >> 2;                   // 0..63
            int c8  = (t & 3) * 8;
            const float* bp = &B[(size_t)(ccol + row) * K + kt + c8];
            float4 b0 = *reinterpret_cast<const float4*>(bp);
            float4 b1 = *reinterpret_cast<const float4*>(bp + 4);
            unsigned* d = reinterpret_cast<unsigned*>(&Bsh[row * HSG + c8]);
            d[0] = h2u(b0.x, b0.y); d[1] = h2u(b0.z, b0.w);
            d[2] = h2u(b1.x, b1.y); d[3] = h2u(b1.z, b1.w);
        }
        __syncthreads();

        #pragma unroll
        for (int kc = 0; kc < 2; kc++) {
            unsigned a[2][4];
            #pragma unroll
            for (int mf = 0; mf < 2; mf++) {
                int row = warp * 32 + mf * 16 + l7 + se1 * 8;
                int col = kc * 16 + se2 * 8;
                ldsm_x4(a[mf], Ab + 2u * (row * HSG + col));
            }
            #pragma unroll
            for (int j = 0; j < 4; j++) {
                unsigned b[4];
                int row = (j * 2 + se2) * 8 + l7;
                int col = kc * 16 + se1 * 8;
                ldsm_x4(b, Bb + 2u * (row * HSG + col));
                mma_f16(acc[0][2 * j    ], a[0], b[0], b[1]);
                mma_f16(acc[0][2 * j + 1], a[0], b[2], b[3]);
                mma_f16(acc[1][2 * j    ], a[1], b[0], b[1]);
                mma_f16(acc[1][2 * j + 1], a[1], b[2], b[3]);
            }
        }
        __syncthreads();
    }

    #pragma unroll
    for (int mf = 0; mf < 2; mf++) {
        int row0 = crow + warp * 32 + mf * 16 + lr;
        #pragma unroll
        for (int nc = 0; nc < 8; nc++) {
            int col = ccol + nc * 8 + 2 * lc;
            float b0 = bias[col], b1 = bias[col + 1];
            float2 v0, v1;
            v0.x = (acc[mf][nc][0] + b0) * scale;
            v0.y = (acc[mf][nc][1] + b1) * scale;
            v1.x = (acc[mf][nc][2] + b0) * scale;
            v1.y = (acc[mf][nc][3] + b1) * scale;
            *reinterpret_cast<float2*>(&C[(size_t)row0 * N + col])       = v0;
            *reinterpret_cast<float2*>(&C[(size_t)(row0 + 8) * N + col]) = v1;
        }
    }
}

// ============================================================================
// Flash attention, fp16 mma + ldmatrix.x4 (b-frags loaded in nc-pairs).
// 128 threads / 4 warps, warp M=16 -> BQ=64, key tiles FBK=64.
// ============================================================================
#define FBQ 64
#define FBK 64
#define HS 72    // half stride per row

__global__ __launch_bounds__(128)
void flash_f16(const float* __restrict__ Q, const float* __restrict__ K,
               const float* __restrict__ V, const int* __restrict__ mask,
               float* __restrict__ Ctx) {
    __shared__ __half Ksh[64 * HS];
    __shared__ __half Vsh[64 * HS];
    __shared__ __half Psh[4 * 16 * HS];
    __shared__ float  msk[64];

    const int h  = blockIdx.y;
    const int q0 = blockIdx.x * FBQ;
    const int tid  = threadIdx.x;
    const int warp = tid >> 5;
    const int lane = tid & 31;
    const int lr = lane >> 2;
    const int lc = lane & 3;

    const uint32_t Kb = smem_u32(Ksh);
    const uint32_t Vb = smem_u32(Vsh);
    const uint32_t Pb = smem_u32(Psh);

    const int l7  = lane & 7;
    const int l15 = lane & 15;
    const int se1 = (lane >> 3) & 1;
    const int se2 = (lane >> 4) & 1;

    // Q fragments in registers (fp16): 4 kc-groups x 4 half2
    unsigned aq[4][4];
    {
        const float* Qp = Q + (size_t)(q0 + warp * 16) * D_MODEL + h * D_HEAD;
        #pragma unroll
        for (int kc = 0; kc < 4; kc++) {
            float2 x0 = *reinterpret_cast<const float2*>(&Qp[(size_t)(lr    ) * D_MODEL + kc * 16 + 2 * lc    ]);
            float2 x1 = *reinterpret_cast<const float2*>(&Qp[(size_t)(lr + 8) * D_MODEL + kc * 16 + 2 * lc    ]);
            float2 x2 = *reinterpret_cast<const float2*>(&Qp[(size_t)(lr    ) * D_MODEL + kc * 16 + 2 * lc + 8]);
            float2 x3 = *reinterpret_cast<const float2*>(&Qp[(size_t)(lr + 8) * D_MODEL + kc * 16 + 2 * lc + 8]);
            aq[kc][0] = h2u(x0.x, x0.y);
            aq[kc][1] = h2u(x1.x, x1.y);
            aq[kc][2] = h2u(x2.x, x2.y);
            aq[kc][3] = h2u(x3.x, x3.y);
        }
    }

    float o[8][4];
    #pragma unroll
    for (int nc = 0; nc < 8; nc++)
        #pragma unroll
        for (int i = 0; i < 4; i++) o[nc][i] = 0.f;
    float m0 = -1e30f, m1 = -1e30f, l0 = 0.f, l1 = 0.f;

    for (int kt = 0; kt < S_LEN; kt += FBK) {
        __syncthreads();
        // stage K and V tiles as fp16 [row][HS]
        #pragma unroll
        for (int it = 0; it < 4; it++) {
            int t = tid + it * 128;            // 0..511
            int row = t >> 3;                   // 0..63
            int c8  = (t & 7) * 8;              // 0..56
            const float* kp = K + (size_t)(kt + row) * D_MODEL + h * D_HEAD + c8;
            const float* vp = V + (size_t)(kt + row) * D_MODEL + h * D_HEAD + c8;
            float4 ka = *reinterpret_cast<const float4*>(kp);
            float4 kb2 = *reinterpret_cast<const float4*>(kp + 4);
            float4 va = *reinterpret_cast<const float4*>(vp);
            float4 vb2 = *reinterpret_cast<const float4*>(vp + 4);
            unsigned* kd = reinterpret_cast<unsigned*>(&Ksh[row * HS + c8]);
            unsigned* vd = reinterpret_cast<unsigned*>(&Vsh[row * HS + c8]);
            kd[0] = h2u(ka.x, ka.y); kd[1] = h2u(ka.z, ka.w);
            kd[2] = h2u(kb2.x, kb2.y); kd[3] = h2u(kb2.z, kb2.w);
            vd[0] = h2u(va.x, va.y); vd[1] = h2u(va.z, va.w);
            vd[2] = h2u(vb2.x, vb2.y); vd[3] = h2u(vb2.z, vb2.w);
        }
        if (tid < FBK) msk[tid] = (mask[kt + tid] != 0) ? 0.f : -1e30f;
        __syncthreads();

        // S = Q @ K^T : B-frags via ldmatrix.x4 (two nc per load)
        float cs[8][4];
        #pragma unroll
        for (int nc = 0; nc < 8; nc++)
            #pragma unroll
            for (int i = 0; i < 4; i++) cs[nc][i] = 0.f;
        #pragma unroll
        for (int kc = 0; kc < 4; kc++) {
            #pragma unroll
            for (int j = 0; j < 4; j++) {
                unsigned b[4];
                int row = (j * 2 + se2) * 8 + l7;
                int col = kc * 16 + se1 * 8;
                ldsm_x4(b, Kb + 2u * (row * HS + col));
                mma_f16(cs[2 * j    ], aq[kc], b[0], b[1]);
                mma_f16(cs[2 * j + 1], aq[kc], b[2], b[3]);
            }
        }

        // mask add
        #pragma unroll
        for (int nc = 0; nc < 8; nc++) {
            float mk0 = msk[nc * 8 + 2 * lc];
            float mk1 = msk[nc * 8 + 2 * lc + 1];
            cs[nc][0] += mk0; cs[nc][1] += mk1;
            cs[nc][2] += mk0; cs[nc][3] += mk1;
        }

        // online softmax (fp32)
        float mx0 = -1e30f, mx1 = -1e30f;
        #pragma unroll
        for (int nc = 0; nc < 8; nc++) {
            mx0 = fmaxf(mx0, fmaxf(cs[nc][0], cs[nc][1]));
            mx1 = fmaxf(mx1, fmaxf(cs[nc][2], cs[nc][3]));
        }
        mx0 = fmaxf(mx0, __shfl_xor_sync(0xffffffff, mx0, 1));
        mx0 = fmaxf(mx0, __shfl_xor_sync(0xffffffff, mx0, 2));
        mx1 = fmaxf(mx1, __shfl_xor_sync(0xffffffff, mx1, 1));
        mx1 = fmaxf(mx1, __shfl_xor_sync(0xffffffff, mx1, 2));

        float m0n = fmaxf(m0, mx0);
        float m1n = fmaxf(m1, mx1);
        float corr0 = __expf(m0 - m0n);
        float corr1 = __expf(m1 - m1n);
        m0 = m0n; m1 = m1n;
        l0 *= corr0; l1 *= corr1;
        #pragma unroll
        for (int nc = 0; nc < 8; nc++) {
            o[nc][0] *= corr0; o[nc][1] *= corr0;
            o[nc][2] *= corr1; o[nc][3] *= corr1;
        }

        // P = exp(S - m) -> fp16 per-warp smem tile
        __half* Pw = Psh + warp * 16 * HS;
        #pragma unroll
        for (int nc = 0; nc < 8; nc++) {
            float p0 = __expf(cs[nc][0] - m0);
            float p1 = __expf(cs[nc][1] - m0);
            float p2 = __expf(cs[nc][2] - m1);
            float p3 = __expf(cs[nc][3] - m1);
            l0 += p0 + p1;
            l1 += p2 + p3;
            *reinterpret_cast<unsigned*>(&Pw[(lr    ) * HS + nc * 8 + 2 * lc]) = h2u(p0, p1);
            *reinterpret_cast<unsigned*>(&Pw[(lr + 8) * HS + nc * 8 + 2 * lc]) = h2u(p2, p3);
        }
        __syncwarp();

        // O += P @ V : A via ldmatrix.x4 on P, B via ldmatrix.x4.trans on V (two nc)
        #pragma unroll
        for (int kc = 0; kc < 4; kc++) {
            unsigned a[4];
            {
                int row = warp * 16 + l7 + se1 * 8;
                int col = kc * 16 + se2 * 8;
                ldsm_x4(a, Pb + 2u * (row * HS + col));
            }
            #pragma unroll
            for (int j = 0; j < 4; j++) {
                unsigned b[4];
                int row = kc * 16 + l15;
                int col = (j * 2 + se2) * 8;
                ldsm_x4_t(b, Vb + 2u * (row * HS + col));
                mma_f16(o[2 * j    ], a, b[0], b[1]);
                mma_f16(o[2 * j + 1], a, b[2], b[3]);
            }
        }
    }

    // finalize
    l0 += __shfl_xor_sync(0xffffffff, l0, 1);
    l0 += __shfl_xor_sync(0xffffffff, l0, 2);
    l1 += __shfl_xor_sync(0xffffffff, l1, 1);
    l1 += __shfl_xor_sync(0xffffffff, l1, 2);
    float inv0 = 1.f / l0;
    float inv1 = 1.f / l1;

    float* O0 = Ctx + (size_t)(q0 + warp * 16 + lr) * D_MODEL + h * D_HEAD;
    float* O1 = O0 + (size_t)8 * D_MODEL;
    #pragma unroll
    for (int nc = 0; nc < 8; nc++) {
        int col = nc * 8 + 2 * lc;
        float2 v0; v0.x = o[nc][0] * inv0; v0.y = o[nc][1] * inv0;
        float2 v1; v1.x = o[nc][2] * inv1; v1.y = o[nc][3] * inv1;
        *reinterpret_cast<float2*>(&O0[col]) = v0;
        *reinterpret_cast<float2*>(&O1[col]) = v1;
    }
}

// ---------------- launch ----------------
extern "C" void kernel_launch(void* const* d_in, const int* in_sizes, int n_in,
                              void* d_out, int out_size) {
    const float* query = (const float*)d_in[0];
    const float* key   = (const float*)d_in[1];
    const float* value = (const float*)d_in[2];
    const int*   mask  = (const int*)d_in[3];
    const float* Wq = (const float*)d_in[4];
    const float* bq = (const float*)d_in[5];
    const float* Wk = (const float*)d_in[6];
    const float* bk = (const float*)d_in[7];
    const float* Wv = (const float*)d_in[8];
    const float* bv = (const float*)d_in[9];
    const float* Wo = (const float*)d_in[10];
    const float* bo = (const float*)d_in[11];
    float* out = (float*)d_out;

    void *pQ, *pK, *pV, *pC;
    cudaGetSymbolAddress(&pQ, g_Q);
    cudaGetSymbolAddress(&pK, g_K);
    cudaGetSymbolAddress(&pV, g_V);
    cudaGetSymbolAddress(&pC, g_CTX);

    dim3 gridP(D_MODEL / GBN, S_LEN / GBM);   // (12, 32)
    const float qscale = 1.0f / 8.0f;

    gemm_f16<<<gridP, 128>>>(query, Wq, bq, (float*)pQ, S_LEN, D_MODEL, D_MODEL, qscale);
    gemm_f16<<<gridP, 128>>>(key,   Wk, bk, (float*)pK, S_LEN, D_MODEL, D_MODEL, 1.0f);
    gemm_f16<<<gridP, 128>>>(value, Wv, bv, (float*)pV, S_LEN, D_MODEL, D_MODEL, 1.0f);

    dim3 gridA(S_LEN / FBQ, N_HEADS);         // (64, 12)
    flash_f16<<<gridA, 128>>>((const float*)pQ, (const float*)pK,
                              (const float*)pV, mask, (float*)pC);

    gemm_f16<<<gridP, 128>>>((const float*)pC, Wo, bo, out, S_LEN, D_MODEL, D_MODEL, 1.0f);
}

// round 9
// speedup vs baseline: 4.0338x; 1.2351x over previous
#include <cuda_runtime.h>
#include <cuda_fp16.h>
#include <math.h>
#include <stdint.h>

#define S_LEN 4096
#define D_MODEL 768
#define N_HEADS 12
#define D_HEAD 64

// ---------------- scratch (no allocations allowed) ----------------
__device__ __half g_Q[S_LEN * D_MODEL];
__device__ __half g_K[S_LEN * D_MODEL];
__device__ __half g_V[S_LEN * D_MODEL];
__device__ float  g_CTX[S_LEN * D_MODEL];

// ---------------- fp16 helpers ----------------
__device__ __forceinline__ void mma_f16(float* c, const unsigned* a, unsigned b0, unsigned b1) {
    asm volatile(
        "mma.sync.aligned.m16n8k16.row.col.f32.f16.f16.f32 "
        "{%0,%1,%2,%3}, {%4,%5,%6,%7}, {%8,%9}, {%0,%1,%2,%3};\n"
        : "+f"(c[0]), "+f"(c[1]), "+f"(c[2]), "+f"(c[3])
        : "r"(a[0]), "r"(a[1]), "r"(a[2]), "r"(a[3]), "r"(b0), "r"(b1));
}
__device__ __forceinline__ uint32_t smem_u32(const void* p) {
    uint32_t a;
    asm("{ .reg .u64 t; cvta.to.shared.u64 t, %1; cvt.u32.u64 %0, t; }" : "=r"(a) : "l"(p));
    return a;
}
__device__ __forceinline__ void ldsm_x4(unsigned* r, uint32_t addr) {
    asm volatile("ldmatrix.sync.aligned.m8n8.x4.shared.b16 {%0,%1,%2,%3}, [%4];"
                 : "=r"(r[0]), "=r"(r[1]), "=r"(r[2]), "=r"(r[3]) : "r"(addr));
}
__device__ __forceinline__ void ldsm_x4_t(unsigned* r, uint32_t addr) {
    asm volatile("ldmatrix.sync.aligned.m8n8.x4.trans.shared.b16 {%0,%1,%2,%3}, [%4];"
                 : "=r"(r[0]), "=r"(r[1]), "=r"(r[2]), "=r"(r[3]) : "r"(addr));
}
__device__ __forceinline__ unsigned h2u(float x, float y) {
    __half2 h = __floats2half2_rn(x, y);
    return *reinterpret_cast<unsigned*>(&h);
}
__device__ __forceinline__ void cp16(uint32_t dst, const void* src) {
    asm volatile("cp.async.cg.shared.global [%0], [%1], 16;\n" :: "r"(dst), "l"(src));
}
#define CP_COMMIT() asm volatile("cp.async.commit_group;\n" ::: "memory")
#define CP_WAIT0()  asm volatile("cp.async.wait_group 0;\n" ::: "memory")
#define CP_WAIT1()  asm volatile("cp.async.wait_group 1;\n" ::: "memory")

// ============================================================================
// GEMM (fp16 mma m16n8k16 + ldmatrix): acc = A[M,K] @ B[N,K]^T + bias, *scale
// 128 threads / 4 warps. BM=128 (warp M=32), BN=64, BK=32. fp32 accumulate.
// Two epilogues: fp32 out (final projection) and fp16 out (Q/K/V).
// ============================================================================
#define GBM 128
#define GBN 64
#define GBK 32
#define HSG 40   // half stride per staged row

template <typename OutT>
__global__ __launch_bounds__(128)
void gemm_f16(const float* __restrict__ A, const float* __restrict__ B,
              const float* __restrict__ bias, OutT* __restrict__ C,
              int M, int N, int K, float scale) {
    __shared__ __half Ash[GBM * HSG];
    __shared__ __half Bsh[GBN * HSG];

    const int tid  = threadIdx.x;
    const int warp = tid >> 5;
    const int lane = tid & 31;
    const int lr = lane >> 2;
    const int lc = lane & 3;
    const int l7 = lane & 7;
    const int se1 = (lane >> 3) & 1;
    const int se2 = (lane >> 4) & 1;

    const uint32_t Ab = smem_u32(Ash);
    const uint32_t Bb = smem_u32(Bsh);

    const int crow = blockIdx.y * GBM;
    const int ccol = blockIdx.x * GBN;

    float acc[2][8][4];
    #pragma unroll
    for (int mf = 0; mf < 2; mf++)
        #pragma unroll
        for (int nc = 0; nc < 8; nc++)
            #pragma unroll
            for (int i = 0; i < 4; i++) acc[mf][nc][i] = 0.f;

    for (int kt = 0; kt < K; kt += GBK) {
        #pragma unroll
        for (int it = 0; it < 4; it++) {
            int t = tid + it * 128;
            int row = t >> 2;
            int c8  = (t & 3) * 8;
            const float* ap = &A[(size_t)(crow + row) * K + kt + c8];
            float4 a0 = *reinterpret_cast<const float4*>(ap);
            float4 a1 = *reinterpret_cast<const float4*>(ap + 4);
            unsigned* d = reinterpret_cast<unsigned*>(&Ash[row * HSG + c8]);
            d[0] = h2u(a0.x, a0.y); d[1] = h2u(a0.z, a0.w);
            d[2] = h2u(a1.x, a1.y); d[3] = h2u(a1.z, a1.w);
        }
        #pragma unroll
        for (int it = 0; it < 2; it++) {
            int t = tid + it * 128;
            int row = t >> 2;
            int c8  = (t & 3) * 8;
            const float* bp = &B[(size_t)(ccol + row) * K + kt + c8];
            float4 b0 = *reinterpret_cast<const float4*>(bp);
            float4 b1 = *reinterpret_cast<const float4*>(bp + 4);
            unsigned* d = reinterpret_cast<unsigned*>(&Bsh[row * HSG + c8]);
            d[0] = h2u(b0.x, b0.y); d[1] = h2u(b0.z, b0.w);
            d[2] = h2u(b1.x, b1.y); d[3] = h2u(b1.z, b1.w);
        }
        __syncthreads();

        #pragma unroll
        for (int kc = 0; kc < 2; kc++) {
            unsigned a[2][4];
            #pragma unroll
            for (int mf = 0; mf < 2; mf++) {
                int row = warp * 32 + mf * 16 + l7 + se1 * 8;
                int col = kc * 16 + se2 * 8;
                ldsm_x4(a[mf], Ab + 2u * (row * HSG + col));
            }
            #pragma unroll
            for (int j = 0; j < 4; j++) {
                unsigned b[4];
                int row = (j * 2 + se2) * 8 + l7;
                int col = kc * 16 + se1 * 8;
                ldsm_x4(b, Bb + 2u * (row * HSG + col));
                mma_f16(acc[0][2 * j    ], a[0], b[0], b[1]);
                mma_f16(acc[0][2 * j + 1], a[0], b[2], b[3]);
                mma_f16(acc[1][2 * j    ], a[1], b[0], b[1]);
                mma_f16(acc[1][2 * j + 1], a[1], b[2], b[3]);
            }
        }
        __syncthreads();
    }

    #pragma unroll
    for (int mf = 0; mf < 2; mf++) {
        int row0 = crow + warp * 32 + mf * 16 + lr;
        #pragma unroll
        for (int nc = 0; nc < 8; nc++) {
            int col = ccol + nc * 8 + 2 * lc;
            float b0 = bias[col], b1 = bias[col + 1];
            float r00 = (acc[mf][nc][0] + b0) * scale;
            float r01 = (acc[mf][nc][1] + b1) * scale;
            float r10 = (acc[mf][nc][2] + b0) * scale;
            float r11 = (acc[mf][nc][3] + b1) * scale;
            if (sizeof(OutT) == 4) {
                float2 v0; v0.x = r00; v0.y = r01;
                float2 v1; v1.x = r10; v1.y = r11;
                *reinterpret_cast<float2*>(&((float*)C)[(size_t)row0 * N + col])       = v0;
                *reinterpret_cast<float2*>(&((float*)C)[(size_t)(row0 + 8) * N + col]) = v1;
            } else {
                *reinterpret_cast<unsigned*>(&((__half*)C)[(size_t)row0 * N + col])       = h2u(r00, r01);
                *reinterpret_cast<unsigned*>(&((__half*)C)[(size_t)(row0 + 8) * N + col]) = h2u(r10, r11);
            }
        }
    }
}

// ============================================================================
// Flash attention, fp16 mma + ldmatrix.x4, cp.async double-buffered K/V.
// 128 threads / 4 warps, warp M=16 -> BQ=64, key tiles FBK=64.
// ============================================================================
#define FBQ 64
#define FBK 64
#define HS 72        // half stride per row (144B, 16B-aligned chunks)
#define NTILES (S_LEN / FBK)

__global__ __launch_bounds__(128)
void flash_f16(const __half* __restrict__ Q, const __half* __restrict__ K,
               const __half* __restrict__ V, const int* __restrict__ mask,
               float* __restrict__ Ctx) {
    __shared__ __half Ksh[2][64 * HS];
    __shared__ __half Vsh[2][64 * HS];
    __shared__ __half Psh[4 * 16 * HS];
    __shared__ float  msk[2][64];

    const int h  = blockIdx.y;
    const int q0 = blockIdx.x * FBQ;
    const int tid  = threadIdx.x;
    const int warp = tid >> 5;
    const int lane = tid & 31;
    const int lr = lane >> 2;
    const int lc = lane & 3;

    const uint32_t Kb0 = smem_u32(Ksh[0]);
    const uint32_t Kb1 = smem_u32(Ksh[1]);
    const uint32_t Vb0 = smem_u32(Vsh[0]);
    const uint32_t Vb1 = smem_u32(Vsh[1]);
    const uint32_t Pb  = smem_u32(Psh);

    const int l7  = lane & 7;
    const int l15 = lane & 15;
    const int se1 = (lane >> 3) & 1;
    const int se2 = (lane >> 4) & 1;

    // staging coords for this thread (4 chunks of 16B per tile per tensor)
    const int srow = tid >> 3;          // base row advanced by +16 per it? no: t=tid+it*128
    // prologue: stage tile 0 into buffer 0
    {
        #pragma unroll
        for (int it = 0; it < 4; it++) {
            int t = tid + it * 128;
            int row = t >> 3;
            int c8  = (t & 7) * 8;
            const __half* kp = K + (size_t)row * D_MODEL + h * D_HEAD + c8;
            const __half* vp = V + (size_t)row * D_MODEL + h * D_HEAD + c8;
            cp16(Kb0 + 2u * (row * HS + c8), kp);
            cp16(Vb0 + 2u * (row * HS + c8), vp);
        }
        CP_COMMIT();
        if (tid < FBK) msk[0][tid] = (mask[tid] != 0) ? 0.f : -1e30f;
    }
    (void)srow;

    // Q fragments in registers (fp16 direct loads)
    unsigned aq[4][4];
    {
        const __half* Qp = Q + (size_t)(q0 + warp * 16) * D_MODEL + h * D_HEAD;
        #pragma unroll
        for (int kc = 0; kc < 4; kc++) {
            aq[kc][0] = *reinterpret_cast<const unsigned*>(&Qp[(size_t)(lr    ) * D_MODEL + kc * 16 + 2 * lc    ]);
            aq[kc][1] = *reinterpret_cast<const unsigned*>(&Qp[(size_t)(lr + 8) * D_MODEL + kc * 16 + 2 * lc    ]);
            aq[kc][2] = *reinterpret_cast<const unsigned*>(&Qp[(size_t)(lr    ) * D_MODEL + kc * 16 + 2 * lc + 8]);
            aq[kc][3] = *reinterpret_cast<const unsigned*>(&Qp[(size_t)(lr + 8) * D_MODEL + kc * 16 + 2 * lc + 8]);
        }
    }

    float o[8][4];
    #pragma unroll
    for (int nc = 0; nc < 8; nc++)
        #pragma unroll
        for (int i = 0; i < 4; i++) o[nc][i] = 0.f;
    float m0 = -1e30f, m1 = -1e30f, l0 = 0.f, l1 = 0.f;

    for (int tt = 0; tt < NTILES; tt++) {
        const int cur = tt & 1;
        const uint32_t Kb = cur ? Kb1 : Kb0;
        const uint32_t Vb = cur ? Vb1 : Vb0;

        // prefetch next tile into the other buffer
        if (tt + 1 < NTILES) {
            const int kt1 = (tt + 1) * FBK;
            const uint32_t Kn = cur ? Kb0 : Kb1;
            const uint32_t Vn = cur ? Vb0 : Vb1;
            #pragma unroll
            for (int it = 0; it < 4; it++) {
                int t = tid + it * 128;
                int row = t >> 3;
                int c8  = (t & 7) * 8;
                const __half* kp = K + (size_t)(kt1 + row) * D_MODEL + h * D_HEAD + c8;
                const __half* vp = V + (size_t)(kt1 + row) * D_MODEL + h * D_HEAD + c8;
                cp16(Kn + 2u * (row * HS + c8), kp);
                cp16(Vn + 2u * (row * HS + c8), vp);
            }
            CP_COMMIT();
            if (tid < FBK) msk[cur ^ 1][tid] = (mask[kt1 + tid] != 0) ? 0.f : -1e30f;
            CP_WAIT1();
        } else {
            CP_WAIT0();
        }
        __syncthreads();

        // S = Q @ K^T
        float cs[8][4];
        #pragma unroll
        for (int nc = 0; nc < 8; nc++)
            #pragma unroll
            for (int i = 0; i < 4; i++) cs[nc][i] = 0.f;
        #pragma unroll
        for (int kc = 0; kc < 4; kc++) {
            #pragma unroll
            for (int j = 0; j < 4; j++) {
                unsigned b[4];
                int row = (j * 2 + se2) * 8 + l7;
                int col = kc * 16 + se1 * 8;
                ldsm_x4(b, Kb + 2u * (row * HS + col));
                mma_f16(cs[2 * j    ], aq[kc], b[0], b[1]);
                mma_f16(cs[2 * j + 1], aq[kc], b[2], b[3]);
            }
        }

        // mask add
        #pragma unroll
        for (int nc = 0; nc < 8; nc++) {
            float mk0 = msk[cur][nc * 8 + 2 * lc];
            float mk1 = msk[cur][nc * 8 + 2 * lc + 1];
            cs[nc][0] += mk0; cs[nc][1] += mk1;
            cs[nc][2] += mk0; cs[nc][3] += mk1;
        }

        // online softmax (fp32)
        float mx0 = -1e30f, mx1 = -1e30f;
        #pragma unroll
        for (int nc = 0; nc < 8; nc++) {
            mx0 = fmaxf(mx0, fmaxf(cs[nc][0], cs[nc][1]));
            mx1 = fmaxf(mx1, fmaxf(cs[nc][2], cs[nc][3]));
        }
        mx0 = fmaxf(mx0, __shfl_xor_sync(0xffffffff, mx0, 1));
        mx0 = fmaxf(mx0, __shfl_xor_sync(0xffffffff, mx0, 2));
        mx1 = fmaxf(mx1, __shfl_xor_sync(0xffffffff, mx1, 1));
        mx1 = fmaxf(mx1, __shfl_xor_sync(0xffffffff, mx1, 2));

        float m0n = fmaxf(m0, mx0);
        float m1n = fmaxf(m1, mx1);
        float corr0 = __expf(m0 - m0n);
        float corr1 = __expf(m1 - m1n);
        m0 = m0n; m1 = m1n;
        l0 *= corr0; l1 *= corr1;
        #pragma unroll
        for (int nc = 0; nc < 8; nc++) {
            o[nc][0] *= corr0; o[nc][1] *= corr0;
            o[nc][2] *= corr1; o[nc][3] *= corr1;
        }

        // P = exp(S - m) -> fp16 per-warp smem tile
        __half* Pw = Psh + warp * 16 * HS;
        #pragma unroll
        for (int nc = 0; nc < 8; nc++) {
            float p0 = __expf(cs[nc][0] - m0);
            float p1 = __expf(cs[nc][1] - m0);
            float p2 = __expf(cs[nc][2] - m1);
            float p3 = __expf(cs[nc][3] - m1);
            l0 += p0 + p1;
            l1 += p2 + p3;
            *reinterpret_cast<unsigned*>(&Pw[(lr    ) * HS + nc * 8 + 2 * lc]) = h2u(p0, p1);
            *reinterpret_cast<unsigned*>(&Pw[(lr + 8) * HS + nc * 8 + 2 * lc]) = h2u(p2, p3);
        }
        __syncwarp();

        // O += P @ V
        #pragma unroll
        for (int kc = 0; kc < 4; kc++) {
            unsigned a[4];
            {
                int row = warp * 16 + l7 + se1 * 8;
                int col = kc * 16 + se2 * 8;
                ldsm_x4(a, Pb + 2u * (row * HS + col));
            }
            #pragma unroll
            for (int j = 0; j < 4; j++) {
                unsigned b[4];
                int row = kc * 16 + l15;
                int col = (j * 2 + se2) * 8;
                ldsm_x4_t(b, Vb + 2u * (row * HS + col));
                mma_f16(o[2 * j    ], a, b[0], b[1]);
                mma_f16(o[2 * j + 1], a, b[2], b[3]);
            }
        }
        __syncthreads();   // protect buffer reuse by next iteration's prefetch
    }

    // finalize
    l0 += __shfl_xor_sync(0xffffffff, l0, 1);
    l0 += __shfl_xor_sync(0xffffffff, l0, 2);
    l1 += __shfl_xor_sync(0xffffffff, l1, 1);
    l1 += __shfl_xor_sync(0xffffffff, l1, 2);
    float inv0 = 1.f / l0;
    float inv1 = 1.f / l1;

    float* O0 = Ctx + (size_t)(q0 + warp * 16 + lr) * D_MODEL + h * D_HEAD;
    float* O1 = O0 + (size_t)8 * D_MODEL;
    #pragma unroll
    for (int nc = 0; nc < 8; nc++) {
        int col = nc * 8 + 2 * lc;
        float2 v0; v0.x = o[nc][0] * inv0; v0.y = o[nc][1] * inv0;
        float2 v1; v1.x = o[nc][2] * inv1; v1.y = o[nc][3] * inv1;
        *reinterpret_cast<float2*>(&O0[col]) = v0;
        *reinterpret_cast<float2*>(&O1[col]) = v1;
    }
}

// ---------------- launch ----------------
extern "C" void kernel_launch(void* const* d_in, const int* in_sizes, int n_in,
                              void* d_out, int out_size) {
    const float* query = (const float*)d_in[0];
    const float* key   = (const float*)d_in[1];
    const float* value = (const float*)d_in[2];
    const int*   mask  = (const int*)d_in[3];
    const float* Wq = (const float*)d_in[4];
    const float* bq = (const float*)d_in[5];
    const float* Wk = (const float*)d_in[6];
    const float* bk = (const float*)d_in[7];
    const float* Wv = (const float*)d_in[8];
    const float* bv = (const float*)d_in[9];
    const float* Wo = (const float*)d_in[10];
    const float* bo = (const float*)d_in[11];
    float* out = (float*)d_out;

    void *pQ, *pK, *pV, *pC;
    cudaGetSymbolAddress(&pQ, g_Q);
    cudaGetSymbolAddress(&pK, g_K);
    cudaGetSymbolAddress(&pV, g_V);
    cudaGetSymbolAddress(&pC, g_CTX);

    dim3 gridP(D_MODEL / GBN, S_LEN / GBM);   // (12, 32)
    const float qscale = 1.0f / 8.0f;

    gemm_f16<__half><<<gridP, 128>>>(query, Wq, bq, (__half*)pQ, S_LEN, D_MODEL, D_MODEL, qscale);
    gemm_f16<__half><<<gridP, 128>>>(key,   Wk, bk, (__half*)pK, S_LEN, D_MODEL, D_MODEL, 1.0f);
    gemm_f16<__half><<<gridP, 128>>>(value, Wv, bv, (__half*)pV, S_LEN, D_MODEL, D_MODEL, 1.0f);

    dim3 gridA(S_LEN / FBQ, N_HEADS);         // (64, 12)
    flash_f16<<<gridA, 128>>>((const __half*)pQ, (const __half*)pK,
                              (const __half*)pV, mask, (float*)pC);

    gemm_f16<float><<<gridP, 128>>>((const float*)pC, Wo, bo, out, S_LEN, D_MODEL, D_MODEL, 1.0f);
}